// round 12
// baseline (speedup 1.0000x reference)
#include <cuda_runtime.h>
#include <cuda_fp16.h>
#include <cstdint>

#define B_ 2
#define T_ 1024
#define C_ 1024
#define H_ 16
#define D_ 64
#define M_ (B_*T_)   // 2048 rows

// fp16 scratch (static device globals: allocation-free per harness rules)
__device__ __half g_qh [(size_t)M_*C_];
__device__ __half g_kh [(size_t)M_*C_];
__device__ __half g_vh [(size_t)M_*C_];
__device__ __half g_Wkh[(size_t)C_*C_];
__device__ __half g_Wch[(size_t)C_*C_];
__device__ __half g_qp [(size_t)B_*H_*T_*D_]; // q pre-scaled by 0.125*log2(e)
__device__ __half g_kp [(size_t)B_*H_*T_*D_];
__device__ __half g_vp [(size_t)B_*H_*T_*D_];
__device__ __half g_y  [(size_t)M_*C_];
__device__ float  g_part[2][(size_t)M_*C_];   // split-K partials (outproj)

__device__ __forceinline__ uint32_t smem_u32(const void* p) {
    uint32_t a;
    asm("{ .reg .u64 t; cvta.to.shared.u64 t, %1; cvt.u32.u64 %0, t; }"
        : "=r"(a) : "l"(p));
    return a;
}

__device__ __forceinline__ uint32_t packh2(float a, float b) {
    __half2 h = __floats2half2_rn(a, b);
    return *(uint32_t*)&h;
}

__device__ __forceinline__ void mma_f16(
    float* c, uint32_t a0, uint32_t a1, uint32_t a2, uint32_t a3,
    uint32_t b0, uint32_t b1)
{
    asm volatile(
        "mma.sync.aligned.m16n8k16.row.col.f32.f16.f16.f32 "
        "{%0,%1,%2,%3}, {%4,%5,%6,%7}, {%8,%9}, {%0,%1,%2,%3};"
        : "+f"(c[0]), "+f"(c[1]), "+f"(c[2]), "+f"(c[3])
        : "r"(a0), "r"(a1), "r"(a2), "r"(a3), "r"(b0), "r"(b1));
}

__device__ __forceinline__ void ldmat4(uint32_t* r, uint32_t addr) {
    asm volatile("ldmatrix.sync.aligned.m8n8.x4.shared.b16 {%0,%1,%2,%3}, [%4];"
        : "=r"(r[0]), "=r"(r[1]), "=r"(r[2]), "=r"(r[3]) : "r"(addr));
}
__device__ __forceinline__ void ldmat4t(uint32_t* r, uint32_t addr) {
    asm volatile("ldmatrix.sync.aligned.m8n8.x4.trans.shared.b16 {%0,%1,%2,%3}, [%4];"
        : "=r"(r[0]), "=r"(r[1]), "=r"(r[2]), "=r"(r[3]) : "r"(addr));
}

// ---------------------------------------------------------------------------
// fp32 -> fp16 conversion of all GEMM inputs
// ---------------------------------------------------------------------------
__global__ void __launch_bounds__(256)
cvt_kernel(const float* __restrict__ q, const float* __restrict__ k,
           const float* __restrict__ v, const float* __restrict__ Wk,
           const float* __restrict__ Wc)
{
    const float* src; __half* dst; int n;
    switch (blockIdx.y) {
        case 0: src = q;  dst = g_qh;  n = M_*C_; break;
        case 1: src = k;  dst = g_kh;  n = M_*C_; break;
        case 2: src = v;  dst = g_vh;  n = M_*C_; break;
        case 3: src = Wk; dst = g_Wkh; n = C_*C_; break;
        default: src = Wc; dst = g_Wch; n = C_*C_; break;
    }
    int i = (blockIdx.x * 256 + threadIdx.x) * 4;
    if (i < n) {
        float4 f = *(const float4*)(src + i);
        *(__half2*)(dst + i)     = __floats2half2_rn(f.x, f.y);
        *(__half2*)(dst + i + 2) = __floats2half2_rn(f.z, f.w);
    }
}

// ---------------------------------------------------------------------------
// fp16 mma.sync GEMM: out = Xh[M, K] @ Wh[N, K]^T (+ bias)
// CTA 128x64, 128 threads (4 warps, warp tile 64x32), BK=64 (128B rows),
// 3-stage cp.async pipeline with post-barrier prefetch.
// out_mode 0: fp32 [M,N]+bias; 1: fp16 scatter [B,H,T,D] *oscale; 2: raw fp32.
// ---------------------------------------------------------------------------
#define BKg 64
#define A_STAGE 16384                    // 128 rows * 128 B
#define B_STAGE 8192                     // 64 rows * 128 B
#define STAGE_BYTES (A_STAGE + B_STAGE)  // 24576
#define SMEM_GEMM_BYTES (3 * STAGE_BYTES)    // 73728

// swizzled byte offset for (row, 16B-chunk c in 0..7) in a 128B-row tile
__device__ __forceinline__ uint32_t swz128(int row, int c) {
    return (uint32_t)(row * 128 + ((c ^ (row & 7)) << 4));
}

__device__ __forceinline__ void gemm_h(
    const __half* __restrict__ X, const __half* __restrict__ W,
    const float* __restrict__ bias, void* __restrict__ out,
    int out_mode, float oscale, int nch)
{
    extern __shared__ __half smh[];
    const uint32_t sb = smem_u32(smh);

    const int tid  = threadIdx.x;
    const int wid  = tid >> 5;
    const int lane = tid & 31;
    const int warpM = (wid & 1) * 64;
    const int warpN = (wid >> 1) * 32;
    const int m0 = blockIdx.y * 128;
    const int n0 = blockIdx.x * 64;
    const int lr = lane >> 2;
    const int lc = lane & 3;

    float acc[4][4][4];
    #pragma unroll
    for (int i = 0; i < 4; i++)
        #pragma unroll
        for (int j = 0; j < 4; j++)
            #pragma unroll
            for (int e = 0; e < 4; e++) acc[i][j][e] = 0.f;

    const int ldr = tid >> 3;             // 0..15
    const int ldc = tid & 7;              // 16B chunk 0..7
    auto load_chunk = [&](int ch, int st) {
        const uint32_t base = sb + (uint32_t)st * STAGE_BYTES;
        #pragma unroll
        for (int i = 0; i < 8; i++) {     // A: 128 rows
            const int r = ldr + i * 16;
            const __half* gA = X + (size_t)(m0 + r) * C_ + ch * BKg + ldc * 8;
            asm volatile("cp.async.cg.shared.global [%0], [%1], 16;"
                         :: "r"(base + swz128(r, ldc)), "l"(gA));
        }
        #pragma unroll
        for (int i = 0; i < 4; i++) {     // B: 64 rows
            const int r = ldr + i * 16;
            const __half* gB = W + (size_t)(n0 + r) * C_ + ch * BKg + ldc * 8;
            asm volatile("cp.async.cg.shared.global [%0], [%1], 16;"
                         :: "r"(base + A_STAGE + swz128(r, ldc)), "l"(gB));
        }
        asm volatile("cp.async.commit_group;" ::: "memory");
    };

    load_chunk(0, 0);
    if (nch > 1) load_chunk(1, 1);

    for (int ch = 0; ch < nch; ch++) {
        const int st = ch % 3;
        if (ch + 1 < nch)
            asm volatile("cp.async.wait_group 1;" ::: "memory");
        else
            asm volatile("cp.async.wait_group 0;" ::: "memory");
        __syncthreads();
        if (ch + 2 < nch)
            load_chunk(ch + 2, (ch + 2) % 3);

        const uint32_t aB = sb + (uint32_t)st * STAGE_BYTES;
        const uint32_t bB = aB + A_STAGE;

        #pragma unroll
        for (int kk = 0; kk < BKg; kk += 16) {
            const int kc = kk >> 3;
            uint32_t af[4][4], bf[2][4];
            #pragma unroll
            for (int mi = 0; mi < 4; mi++) {
                int row = warpM + mi * 16 + (lane & 15);
                int cc  = kc + (lane >> 4);
                ldmat4(af[mi], aB + swz128(row, cc));
            }
            #pragma unroll
            for (int np = 0; np < 2; np++) {
                int row = warpN + np * 16 + (lane & 7) + ((lane >> 4) & 1) * 8;
                int cc  = kc + ((lane >> 3) & 1);
                ldmat4(bf[np], bB + swz128(row, cc));
            }
            #pragma unroll
            for (int mi = 0; mi < 4; mi++)
                #pragma unroll
                for (int ni = 0; ni < 4; ni++)
                    mma_f16(acc[mi][ni],
                            af[mi][0], af[mi][1], af[mi][2], af[mi][3],
                            bf[ni >> 1][(ni & 1) * 2], bf[ni >> 1][(ni & 1) * 2 + 1]);
        }
    }

    #pragma unroll
    for (int mi = 0; mi < 4; mi++) {
        #pragma unroll
        for (int rr = 0; rr < 2; rr++) {
            const int m = m0 + warpM + mi * 16 + lr + rr * 8;
            #pragma unroll
            for (int ni = 0; ni < 4; ni++) {
                const int n = n0 + warpN + ni * 8 + lc * 2;
                if (out_mode == 2) {
                    float2 vv = { acc[mi][ni][rr*2+0], acc[mi][ni][rr*2+1] };
                    *(float2*)((float*)out + (size_t)m * C_ + n) = vv;
                } else {
                    float vx = (acc[mi][ni][rr*2+0] + bias[n])     * oscale;
                    float vy = (acc[mi][ni][rr*2+1] + bias[n + 1]) * oscale;
                    if (out_mode == 0) {
                        float2 vv = { vx, vy };
                        *(float2*)((float*)out + (size_t)m * C_ + n) = vv;
                    } else {
                        const int b = m >> 10, t = m & (T_ - 1);
                        const int h = n >> 6,  d0 = n & (D_ - 1);
                        *(__half2*)((__half*)out +
                            (((size_t)(b * H_ + h)) * T_ + t) * D_ + d0) =
                            __floats2half2_rn(vx, vy);
                    }
                }
            }
        }
    }
}

__global__ void __launch_bounds__(128, 3)
proj_h_kernel(const float* __restrict__ bk)
{
    const __half* X = (blockIdx.z == 0) ? g_qh : (blockIdx.z == 1) ? g_kh : g_vh;
    __half* O = (blockIdx.z == 0) ? g_qp : (blockIdx.z == 1) ? g_kp : g_vp;
    // fold 1/sqrt(D) * log2(e) into Q so attention works in the log2 domain
    const float sc = (blockIdx.z == 0) ? 0.125f * 1.44269504f : 1.0f;
    gemm_h(X, g_Wkh, bk, O, 1, sc, C_/BKg);
}

// split-K outproj: z = K-half; each writes fp32 partial (no bias)
__global__ void __launch_bounds__(128, 3)
outproj_split_kernel()
{
    const int kz = blockIdx.z;
    gemm_h(g_y + kz * 512, g_Wch + kz * 512, nullptr,
           g_part[kz], 2, 1.0f, 512/BKg);
}

__global__ void __launch_bounds__(256)
outproj_reduce_kernel(const float* __restrict__ bc, float* __restrict__ out)
{
    int i = (blockIdx.x * 256 + threadIdx.x) * 4;
    float4 p0 = *(const float4*)(&g_part[0][i]);
    float4 p1 = *(const float4*)(&g_part[1][i]);
    const float4 bb = *(const float4*)(bc + (i & (C_ - 1)));
    float4 r;
    r.x = p0.x + p1.x + bb.x;
    r.y = p0.y + p1.y + bb.y;
    r.z = p0.z + p1.z + bb.z;
    r.w = p0.w + p1.w + bb.w;
    *(float4*)(out + i) = r;
}

// ---------------------------------------------------------------------------
// fp16 tensor-core causal flash attention, KN=128 keys per iteration
// (one softmax pass + one barrier pair per 128 keys).
// CTA: 64 q-rows of one (b,h); 4 warps x 16 rows; K/V double-buffered.
// ---------------------------------------------------------------------------
#define ASTR 72
#define ROWB (ASTR * 2)                  // bytes per SMEM row (144)
// dynamic SMEM rows: sQ 64 | sK0 128 | sK1 128 | sV0 128 | sV1 128
#define ATT_Q_OFF   0
#define ATT_K_OFF(s) ((64 + (s) * 128) * ROWB)
#define ATT_V_OFF(s) ((320 + (s) * 128) * ROWB)
#define ATT_SMEM_BYTES (576 * ROWB)      // 82944

__global__ void __launch_bounds__(128)
attn_h_kernel()
{
    extern __shared__ __half smha[];
    const uint32_t sb = smem_u32(smha);

    const int qt   = 15 - blockIdx.x;             // heavy tiles first
    const int bh   = blockIdx.y;
    const int tid  = threadIdx.x;
    const int w    = tid >> 5;
    const int lane = tid & 31;
    const int g    = lane >> 2;
    const int lc   = lane & 3;

    const __half* Qg = g_qp + (size_t)bh * T_ * D_;
    const __half* Kg = g_kp + (size_t)bh * T_ * D_;
    const __half* Vg = g_vp + (size_t)bh * T_ * D_;

    const int row0 = qt * 64 + w * 16 + g;
    const int row1 = row0 + 8;

    // load nrows rows (multiple of 64) from src+rbase into smem at byte off
    auto load_rows = [&](const __half* src, uint32_t dstOff, int rbase, int nrows) {
        #pragma unroll
        for (int i = 0; i < 8; i++) {
            int idx = tid + i * 128;                // 0..1023
            int r   = idx >> 3;                     // 0..127
            if (r >= nrows) break;
            int c16 = idx & 7;
            const __half* gp = src + (size_t)(rbase + r) * D_ + c16 * 8;
            asm volatile("cp.async.cg.shared.global [%0], [%1], 16;"
                         :: "r"(sb + dstOff + (uint32_t)(r * ROWB + c16 * 16)), "l"(gp));
        }
    };

    load_rows(Qg, ATT_Q_OFF, qt * 64, 64);
    load_rows(Kg, ATT_K_OFF(0), 0, 128);
    load_rows(Vg, ATT_V_OFF(0), 0, 128);
    asm volatile("cp.async.commit_group;" ::: "memory");

    float o[8][4];
    #pragma unroll
    for (int ni = 0; ni < 8; ni++)
        #pragma unroll
        for (int e = 0; e < 4; e++) o[ni][e] = 0.f;
    float m0 = -1e30f, m1 = -1e30f, l0 = 0.f, l1 = 0.f;

    uint32_t qf[4][4];
    const int nk2 = qt / 2 + 1;                    // 128-key iterations

    for (int kt = 0; kt < nk2; kt++) {
        const int s = kt & 1;
        asm volatile("cp.async.wait_group 0;" ::: "memory");
        __syncthreads();
        if (kt + 1 < nk2) {
            load_rows(Kg, ATT_K_OFF(s ^ 1), (kt + 1) * 128, 128);
            load_rows(Vg, ATT_V_OFF(s ^ 1), (kt + 1) * 128, 128);
            asm volatile("cp.async.commit_group;" ::: "memory");
        }
        if (kt == 0) {
            #pragma unroll
            for (int ks = 0; ks < 4; ks++) {
                int row = w * 16 + (lane & 15);
                int col = ks * 16 + (lane >> 4) * 8;
                ldmat4(qf[ks], sb + ATT_Q_OFF + (uint32_t)(row * ROWB + col * 2));
            }
        }

        const uint32_t kb = sb + ATT_K_OFF(s);
        const uint32_t vb = sb + ATT_V_OFF(s);

        // ---- S = Q K^T over 128 keys (log2-domain) ----
        float p[16][4];
        #pragma unroll
        for (int ni = 0; ni < 16; ni++)
            #pragma unroll
            for (int e = 0; e < 4; e++) p[ni][e] = 0.f;

        #pragma unroll
        for (int ks = 0; ks < 4; ks++) {
            #pragma unroll
            for (int np = 0; np < 8; np++) {
                uint32_t kf[4];
                int row = np * 16 + (lane & 7) + ((lane >> 4) & 1) * 8;
                int col = ks * 16 + ((lane >> 3) & 1) * 8;
                ldmat4(kf, kb + (uint32_t)(row * ROWB + col * 2));
                mma_f16(p[np*2],   qf[ks][0], qf[ks][1], qf[ks][2], qf[ks][3], kf[0], kf[1]);
                mma_f16(p[np*2+1], qf[ks][0], qf[ks][1], qf[ks][2], qf[ks][3], kf[2], kf[3]);
            }
        }

        // ---- causal mask: only the last iteration touches the diagonal ----
        if (kt == nk2 - 1) {
            #pragma unroll
            for (int ni = 0; ni < 16; ni++) {
                const int c = kt * 128 + ni * 8 + lc * 2;
                if (c     > row0) p[ni][0] = -1e30f;
                if (c + 1 > row0) p[ni][1] = -1e30f;
                if (c     > row1) p[ni][2] = -1e30f;
                if (c + 1 > row1) p[ni][3] = -1e30f;
            }
        }

        // ---- online softmax (base-2), one pass per 128 keys ----
        float rm0 = -1e30f, rm1 = -1e30f;
        #pragma unroll
        for (int ni = 0; ni < 16; ni++) {
            rm0 = fmaxf(rm0, fmaxf(p[ni][0], p[ni][1]));
            rm1 = fmaxf(rm1, fmaxf(p[ni][2], p[ni][3]));
        }
        rm0 = fmaxf(rm0, __shfl_xor_sync(0xffffffffu, rm0, 1));
        rm0 = fmaxf(rm0, __shfl_xor_sync(0xffffffffu, rm0, 2));
        rm1 = fmaxf(rm1, __shfl_xor_sync(0xffffffffu, rm1, 1));
        rm1 = fmaxf(rm1, __shfl_xor_sync(0xffffffffu, rm1, 2));

        const float mn0 = fmaxf(m0, rm0);
        const float mn1 = fmaxf(m1, rm1);
        const float corr0 = exp2f(m0 - mn0);
        const float corr1 = exp2f(m1 - mn1);
        m0 = mn0; m1 = mn1;

        uint32_t pe0[16], pe1[16];
        float rs0 = 0.f, rs1 = 0.f;
        #pragma unroll
        for (int ni = 0; ni < 16; ni++) {
            uint32_t ea = packh2(p[ni][0] - m0, p[ni][1] - m0);
            uint32_t eb = packh2(p[ni][2] - m1, p[ni][3] - m1);
            asm("ex2.approx.f16x2 %0, %0;" : "+r"(ea));
            asm("ex2.approx.f16x2 %0, %0;" : "+r"(eb));
            pe0[ni] = ea; pe1[ni] = eb;
            float2 fa = __half22float2(*(__half2*)&ea);
            float2 fb = __half22float2(*(__half2*)&eb);
            rs0 += fa.x + fa.y;
            rs1 += fb.x + fb.y;
        }
        rs0 += __shfl_xor_sync(0xffffffffu, rs0, 1);
        rs0 += __shfl_xor_sync(0xffffffffu, rs0, 2);
        rs1 += __shfl_xor_sync(0xffffffffu, rs1, 1);
        rs1 += __shfl_xor_sync(0xffffffffu, rs1, 2);
        l0 = l0 * corr0 + rs0;
        l1 = l1 * corr1 + rs1;

        #pragma unroll
        for (int ni = 0; ni < 8; ni++) {
            o[ni][0] *= corr0; o[ni][1] *= corr0;
            o[ni][2] *= corr1; o[ni][3] *= corr1;
        }

        // ---- O += P V over k-dim 128 ----
        #pragma unroll
        for (int ks = 0; ks < 8; ks++) {
            uint32_t a0 = pe0[2*ks];
            uint32_t a1 = pe1[2*ks];
            uint32_t a2 = pe0[2*ks+1];
            uint32_t a3 = pe1[2*ks+1];
            #pragma unroll
            for (int np = 0; np < 4; np++) {
                uint32_t vf[4];
                int row = ks * 16 + (lane & 7) + ((lane >> 3) & 1) * 8;
                int col = np * 16 + ((lane >> 4) & 1) * 8;
                ldmat4t(vf, vb + (uint32_t)(row * ROWB + col * 2));
                mma_f16(o[np*2],   a0, a1, a2, a3, vf[0], vf[1]);
                mma_f16(o[np*2+1], a0, a1, a2, a3, vf[2], vf[3]);
            }
        }
    }

    const float inv0 = 1.0f / l0;
    const float inv1 = 1.0f / l1;
    const int b = bh >> 4, h = bh & 15;
    __half* y0 = g_y + ((size_t)(b * T_ + row0)) * C_ + h * D_;
    __half* y1 = g_y + ((size_t)(b * T_ + row1)) * C_ + h * D_;
    #pragma unroll
    for (int ni = 0; ni < 8; ni++) {
        const int d = ni * 8 + lc * 2;
        *(__half2*)(y0 + d) = __floats2half2_rn(o[ni][0] * inv0, o[ni][1] * inv0);
        *(__half2*)(y1 + d) = __floats2half2_rn(o[ni][2] * inv1, o[ni][3] * inv1);
    }
}

// ---------------------------------------------------------------------------
extern "C" void kernel_launch(void* const* d_in, const int* in_sizes, int n_in,
                              void* d_out, int out_size)
{
    const float* q  = (const float*)d_in[0];
    const float* k  = (const float*)d_in[1];
    const float* v  = (const float*)d_in[2];
    // d_in[3] = causal mask (unused: causality handled analytically)
    const float* Wk = (const float*)d_in[4];
    const float* bk = (const float*)d_in[5];
    const float* Wc = (const float*)d_in[6];
    const float* bc = (const float*)d_in[7];
    float* out = (float*)d_out;

    cudaFuncSetAttribute(proj_h_kernel,
                         cudaFuncAttributeMaxDynamicSharedMemorySize, SMEM_GEMM_BYTES);
    cudaFuncSetAttribute(outproj_split_kernel,
                         cudaFuncAttributeMaxDynamicSharedMemorySize, SMEM_GEMM_BYTES);
    cudaFuncSetAttribute(attn_h_kernel,
                         cudaFuncAttributeMaxDynamicSharedMemorySize, ATT_SMEM_BYTES);

    // 0) fp32 -> fp16 conversion of all GEMM operands
    cvt_kernel<<<dim3((M_*C_)/(256*4), 5), 256>>>(q, k, v, Wk, Wc);

    // 1) fused Q/K/V projection (fp16 mma.sync) -> [B,H,T,D] fp16 scratch
    proj_h_kernel<<<dim3(C_/64, M_/128, 3), 128, SMEM_GEMM_BYTES>>>(bk);

    // 2) fp16 tensor-core causal flash attention (KN=128) -> g_y fp16
    attn_h_kernel<<<dim3(16, 32), 128, ATT_SMEM_BYTES>>>();

    // 3) output projection: split-K=2 partials, then deterministic reduce
    outproj_split_kernel<<<dim3(C_/64, M_/128, 2), 128, SMEM_GEMM_BYTES>>>();
    outproj_reduce_kernel<<<(M_*C_)/(256*4), 256>>>(bc, out);
}

// round 13
// speedup vs baseline: 1.0745x; 1.0745x over previous
#include <cuda_runtime.h>
#include <cuda_fp16.h>
#include <cstdint>

#define B_ 2
#define T_ 1024
#define C_ 1024
#define H_ 16
#define D_ 64
#define M_ (B_*T_)   // 2048 rows

// fp16 scratch (static device globals: allocation-free per harness rules)
__device__ __half g_qh [(size_t)M_*C_];
__device__ __half g_kh [(size_t)M_*C_];
__device__ __half g_vh [(size_t)M_*C_];
__device__ __half g_Wkh[(size_t)C_*C_];
__device__ __half g_Wch[(size_t)C_*C_];
__device__ __half g_qp [(size_t)B_*H_*T_*D_]; // q pre-scaled by 0.125*log2(e)
__device__ __half g_kp [(size_t)B_*H_*T_*D_];
__device__ __half g_vp [(size_t)B_*H_*T_*D_];
__device__ __half g_y  [(size_t)M_*C_];

__device__ __forceinline__ uint32_t smem_u32(const void* p) {
    uint32_t a;
    asm("{ .reg .u64 t; cvta.to.shared.u64 t, %1; cvt.u32.u64 %0, t; }"
        : "=r"(a) : "l"(p));
    return a;
}

__device__ __forceinline__ uint32_t packh2(float a, float b) {
    __half2 h = __floats2half2_rn(a, b);
    return *(uint32_t*)&h;
}

__device__ __forceinline__ void mma_f16(
    float* c, uint32_t a0, uint32_t a1, uint32_t a2, uint32_t a3,
    uint32_t b0, uint32_t b1)
{
    asm volatile(
        "mma.sync.aligned.m16n8k16.row.col.f32.f16.f16.f32 "
        "{%0,%1,%2,%3}, {%4,%5,%6,%7}, {%8,%9}, {%0,%1,%2,%3};"
        : "+f"(c[0]), "+f"(c[1]), "+f"(c[2]), "+f"(c[3])
        : "r"(a0), "r"(a1), "r"(a2), "r"(a3), "r"(b0), "r"(b1));
}

__device__ __forceinline__ void ldmat4(uint32_t* r, uint32_t addr) {
    asm volatile("ldmatrix.sync.aligned.m8n8.x4.shared.b16 {%0,%1,%2,%3}, [%4];"
        : "=r"(r[0]), "=r"(r[1]), "=r"(r[2]), "=r"(r[3]) : "r"(addr));
}
__device__ __forceinline__ void ldmat4t(uint32_t* r, uint32_t addr) {
    asm volatile("ldmatrix.sync.aligned.m8n8.x4.trans.shared.b16 {%0,%1,%2,%3}, [%4];"
        : "=r"(r[0]), "=r"(r[1]), "=r"(r[2]), "=r"(r[3]) : "r"(addr));
}

// ---------------------------------------------------------------------------
// fp32 -> fp16 conversion of all GEMM inputs
// ---------------------------------------------------------------------------
__global__ void __launch_bounds__(256)
cvt_kernel(const float* __restrict__ q, const float* __restrict__ k,
           const float* __restrict__ v, const float* __restrict__ Wk,
           const float* __restrict__ Wc)
{
    const float* src; __half* dst; int n;
    switch (blockIdx.y) {
        case 0: src = q;  dst = g_qh;  n = M_*C_; break;
        case 1: src = k;  dst = g_kh;  n = M_*C_; break;
        case 2: src = v;  dst = g_vh;  n = M_*C_; break;
        case 3: src = Wk; dst = g_Wkh; n = C_*C_; break;
        default: src = Wc; dst = g_Wch; n = C_*C_; break;
    }
    int i = (blockIdx.x * 256 + threadIdx.x) * 4;
    if (i < n) {
        float4 f = *(const float4*)(src + i);
        *(__half2*)(dst + i)     = __floats2half2_rn(f.x, f.y);
        *(__half2*)(dst + i + 2) = __floats2half2_rn(f.z, f.w);
    }
}

// swizzled byte offset for (row, 16B-chunk c in 0..7) in a 128B-row tile
__device__ __forceinline__ uint32_t swz128(int row, int c) {
    return (uint32_t)(row * 128 + ((c ^ (row & 7)) << 4));
}

// ---------------------------------------------------------------------------
// Projection GEMM: CTA 128x128, 128 threads (2x2 warps, warp tile 64x64),
// BK=64, 3-stage cp.async pipeline. High MMA-per-LDSM reuse (1:4).
// Writes fp16 scatter into [B,H,T,D] with per-matrix output scale.
// ---------------------------------------------------------------------------
#define BKg 64
#define P_A_STAGE 16384                    // 128 rows * 128 B
#define P_B_STAGE 16384                    // 128 rows * 128 B
#define P_STAGE (P_A_STAGE + P_B_STAGE)    // 32768
#define SMEM_PROJ_BYTES (3 * P_STAGE)      // 98304

__global__ void __launch_bounds__(128, 2)
proj_h_kernel(const float* __restrict__ bk)
{
    const __half* X = (blockIdx.z == 0) ? g_qh : (blockIdx.z == 1) ? g_kh : g_vh;
    __half* out = (blockIdx.z == 0) ? g_qp : (blockIdx.z == 1) ? g_kp : g_vp;
    const float oscale = (blockIdx.z == 0) ? 0.125f * 1.44269504f : 1.0f;
    const __half* W = g_Wkh;

    extern __shared__ __half smh[];
    const uint32_t sb = smem_u32(smh);

    const int tid  = threadIdx.x;
    const int wid  = tid >> 5;
    const int lane = tid & 31;
    const int warpM = (wid & 1) * 64;
    const int warpN = (wid >> 1) * 64;
    const int m0 = blockIdx.y * 128;
    const int n0 = blockIdx.x * 128;
    const int lr = lane >> 2;
    const int lc = lane & 3;

    float acc[4][8][4];
    #pragma unroll
    for (int i = 0; i < 4; i++)
        #pragma unroll
        for (int j = 0; j < 8; j++)
            #pragma unroll
            for (int e = 0; e < 4; e++) acc[i][j][e] = 0.f;

    const int ldr = tid >> 3;             // 0..15
    const int ldc = tid & 7;              // 16B chunk 0..7
    auto load_chunk = [&](int ch, int st) {
        const uint32_t base = sb + (uint32_t)st * P_STAGE;
        #pragma unroll
        for (int i = 0; i < 8; i++) {     // A: 128 rows
            const int r = ldr + i * 16;
            const __half* gA = X + (size_t)(m0 + r) * C_ + ch * BKg + ldc * 8;
            asm volatile("cp.async.cg.shared.global [%0], [%1], 16;"
                         :: "r"(base + swz128(r, ldc)), "l"(gA));
        }
        #pragma unroll
        for (int i = 0; i < 8; i++) {     // B: 128 rows
            const int r = ldr + i * 16;
            const __half* gB = W + (size_t)(n0 + r) * C_ + ch * BKg + ldc * 8;
            asm volatile("cp.async.cg.shared.global [%0], [%1], 16;"
                         :: "r"(base + P_A_STAGE + swz128(r, ldc)), "l"(gB));
        }
        asm volatile("cp.async.commit_group;" ::: "memory");
    };

    const int NCH = C_ / BKg;             // 16
    load_chunk(0, 0);
    load_chunk(1, 1);

    for (int ch = 0; ch < NCH; ch++) {
        const int st = ch % 3;
        if (ch + 1 < NCH)
            asm volatile("cp.async.wait_group 1;" ::: "memory");
        else
            asm volatile("cp.async.wait_group 0;" ::: "memory");
        __syncthreads();
        if (ch + 2 < NCH)
            load_chunk(ch + 2, (ch + 2) % 3);

        const uint32_t aB = sb + (uint32_t)st * P_STAGE;
        const uint32_t bB = aB + P_A_STAGE;

        #pragma unroll
        for (int kk = 0; kk < BKg; kk += 16) {
            const int kc = kk >> 3;
            uint32_t af[4][4], bf[4][4];
            #pragma unroll
            for (int mi = 0; mi < 4; mi++) {
                int row = warpM + mi * 16 + (lane & 15);
                int cc  = kc + (lane >> 4);
                ldmat4(af[mi], aB + swz128(row, cc));
            }
            #pragma unroll
            for (int np = 0; np < 4; np++) {
                int row = warpN + np * 16 + (lane & 7) + ((lane >> 4) & 1) * 8;
                int cc  = kc + ((lane >> 3) & 1);
                ldmat4(bf[np], bB + swz128(row, cc));
            }
            #pragma unroll
            for (int mi = 0; mi < 4; mi++)
                #pragma unroll
                for (int ni = 0; ni < 8; ni++)
                    mma_f16(acc[mi][ni],
                            af[mi][0], af[mi][1], af[mi][2], af[mi][3],
                            bf[ni >> 1][(ni & 1) * 2], bf[ni >> 1][(ni & 1) * 2 + 1]);
        }
    }

    #pragma unroll
    for (int mi = 0; mi < 4; mi++) {
        #pragma unroll
        for (int rr = 0; rr < 2; rr++) {
            const int m = m0 + warpM + mi * 16 + lr + rr * 8;
            const int b = m >> 10, t = m & (T_ - 1);
            #pragma unroll
            for (int ni = 0; ni < 8; ni++) {
                const int n = n0 + warpN + ni * 8 + lc * 2;
                float vx = (acc[mi][ni][rr*2+0] + bk[n])     * oscale;
                float vy = (acc[mi][ni][rr*2+1] + bk[n + 1]) * oscale;
                const int h = n >> 6, d0 = n & (D_ - 1);
                *(__half2*)(out + (((size_t)(b * H_ + h)) * T_ + t) * D_ + d0) =
                    __floats2half2_rn(vx, vy);
            }
        }
    }
}

// ---------------------------------------------------------------------------
// Output projection GEMM (R11 shape): CTA 128x64, 128 threads (2x2 warps,
// warp tile 64x32), BK=64, 3-stage pipeline. fp32 output + bias.
// ---------------------------------------------------------------------------
#define O_A_STAGE 16384                    // 128 rows * 128 B
#define O_B_STAGE 8192                     // 64 rows * 128 B
#define O_STAGE (O_A_STAGE + O_B_STAGE)    // 24576
#define SMEM_OUT_BYTES (3 * O_STAGE)       // 73728

__global__ void __launch_bounds__(128, 3)
outproj_h_kernel(const float* __restrict__ bc, float* __restrict__ out)
{
    extern __shared__ __half smh[];
    const uint32_t sb = smem_u32(smh);
    const __half* X = g_y;
    const __half* W = g_Wch;

    const int tid  = threadIdx.x;
    const int wid  = tid >> 5;
    const int lane = tid & 31;
    const int warpM = (wid & 1) * 64;
    const int warpN = (wid >> 1) * 32;
    const int m0 = blockIdx.y * 128;
    const int n0 = blockIdx.x * 64;
    const int lr = lane >> 2;
    const int lc = lane & 3;

    float acc[4][4][4];
    #pragma unroll
    for (int i = 0; i < 4; i++)
        #pragma unroll
        for (int j = 0; j < 4; j++)
            #pragma unroll
            for (int e = 0; e < 4; e++) acc[i][j][e] = 0.f;

    const int ldr = tid >> 3;
    const int ldc = tid & 7;
    auto load_chunk = [&](int ch, int st) {
        const uint32_t base = sb + (uint32_t)st * O_STAGE;
        #pragma unroll
        for (int i = 0; i < 8; i++) {
            const int r = ldr + i * 16;
            const __half* gA = X + (size_t)(m0 + r) * C_ + ch * BKg + ldc * 8;
            asm volatile("cp.async.cg.shared.global [%0], [%1], 16;"
                         :: "r"(base + swz128(r, ldc)), "l"(gA));
        }
        #pragma unroll
        for (int i = 0; i < 4; i++) {
            const int r = ldr + i * 16;
            const __half* gB = W + (size_t)(n0 + r) * C_ + ch * BKg + ldc * 8;
            asm volatile("cp.async.cg.shared.global [%0], [%1], 16;"
                         :: "r"(base + O_A_STAGE + swz128(r, ldc)), "l"(gB));
        }
        asm volatile("cp.async.commit_group;" ::: "memory");
    };

    const int NCH = C_ / BKg;
    load_chunk(0, 0);
    load_chunk(1, 1);

    for (int ch = 0; ch < NCH; ch++) {
        const int st = ch % 3;
        if (ch + 1 < NCH)
            asm volatile("cp.async.wait_group 1;" ::: "memory");
        else
            asm volatile("cp.async.wait_group 0;" ::: "memory");
        __syncthreads();
        if (ch + 2 < NCH)
            load_chunk(ch + 2, (ch + 2) % 3);

        const uint32_t aB = sb + (uint32_t)st * O_STAGE;
        const uint32_t bB = aB + O_A_STAGE;

        #pragma unroll
        for (int kk = 0; kk < BKg; kk += 16) {
            const int kc = kk >> 3;
            uint32_t af[4][4], bf[2][4];
            #pragma unroll
            for (int mi = 0; mi < 4; mi++) {
                int row = warpM + mi * 16 + (lane & 15);
                int cc  = kc + (lane >> 4);
                ldmat4(af[mi], aB + swz128(row, cc));
            }
            #pragma unroll
            for (int np = 0; np < 2; np++) {
                int row = warpN + np * 16 + (lane & 7) + ((lane >> 4) & 1) * 8;
                int cc  = kc + ((lane >> 3) & 1);
                ldmat4(bf[np], bB + swz128(row, cc));
            }
            #pragma unroll
            for (int mi = 0; mi < 4; mi++)
                #pragma unroll
                for (int ni = 0; ni < 4; ni++)
                    mma_f16(acc[mi][ni],
                            af[mi][0], af[mi][1], af[mi][2], af[mi][3],
                            bf[ni >> 1][(ni & 1) * 2], bf[ni >> 1][(ni & 1) * 2 + 1]);
        }
    }

    #pragma unroll
    for (int mi = 0; mi < 4; mi++) {
        #pragma unroll
        for (int rr = 0; rr < 2; rr++) {
            const int m = m0 + warpM + mi * 16 + lr + rr * 8;
            #pragma unroll
            for (int ni = 0; ni < 4; ni++) {
                const int n = n0 + warpN + ni * 8 + lc * 2;
                float2 vv;
                vv.x = acc[mi][ni][rr*2+0] + bc[n];
                vv.y = acc[mi][ni][rr*2+1] + bc[n + 1];
                *(float2*)(out + (size_t)m * C_ + n) = vv;
            }
        }
    }
}

// ---------------------------------------------------------------------------
// fp16 tensor-core causal flash attention, KN=128 keys per iteration.
// CTA: 64 q-rows of one (b,h); 4 warps x 16 rows; K/V double-buffered.
// ---------------------------------------------------------------------------
#define ASTR 72
#define ROWB (ASTR * 2)                  // bytes per SMEM row (144)
#define ATT_Q_OFF   0
#define ATT_K_OFF(s) ((64 + (s) * 128) * ROWB)
#define ATT_V_OFF(s) ((320 + (s) * 128) * ROWB)
#define ATT_SMEM_BYTES (576 * ROWB)      // 82944

__global__ void __launch_bounds__(128)
attn_h_kernel()
{
    extern __shared__ __half smha[];
    const uint32_t sb = smem_u32(smha);

    const int qt   = 15 - blockIdx.x;             // heavy tiles first
    const int bh   = blockIdx.y;
    const int tid  = threadIdx.x;
    const int w    = tid >> 5;
    const int lane = tid & 31;
    const int g    = lane >> 2;
    const int lc   = lane & 3;

    const __half* Qg = g_qp + (size_t)bh * T_ * D_;
    const __half* Kg = g_kp + (size_t)bh * T_ * D_;
    const __half* Vg = g_vp + (size_t)bh * T_ * D_;

    const int row0 = qt * 64 + w * 16 + g;
    const int row1 = row0 + 8;

    auto load_rows = [&](const __half* src, uint32_t dstOff, int rbase, int nrows) {
        #pragma unroll
        for (int i = 0; i < 8; i++) {
            int idx = tid + i * 128;
            int r   = idx >> 3;
            if (r >= nrows) break;
            int c16 = idx & 7;
            const __half* gp = src + (size_t)(rbase + r) * D_ + c16 * 8;
            asm volatile("cp.async.cg.shared.global [%0], [%1], 16;"
                         :: "r"(sb + dstOff + (uint32_t)(r * ROWB + c16 * 16)), "l"(gp));
        }
    };

    load_rows(Qg, ATT_Q_OFF, qt * 64, 64);
    load_rows(Kg, ATT_K_OFF(0), 0, 128);
    load_rows(Vg, ATT_V_OFF(0), 0, 128);
    asm volatile("cp.async.commit_group;" ::: "memory");

    float o[8][4];
    #pragma unroll
    for (int ni = 0; ni < 8; ni++)
        #pragma unroll
        for (int e = 0; e < 4; e++) o[ni][e] = 0.f;
    float m0 = -1e30f, m1 = -1e30f, l0 = 0.f, l1 = 0.f;

    uint32_t qf[4][4];
    const int nk2 = qt / 2 + 1;                    // 128-key iterations

    for (int kt = 0; kt < nk2; kt++) {
        const int s = kt & 1;
        asm volatile("cp.async.wait_group 0;" ::: "memory");
        __syncthreads();
        if (kt + 1 < nk2) {
            load_rows(Kg, ATT_K_OFF(s ^ 1), (kt + 1) * 128, 128);
            load_rows(Vg, ATT_V_OFF(s ^ 1), (kt + 1) * 128, 128);
            asm volatile("cp.async.commit_group;" ::: "memory");
        }
        if (kt == 0) {
            #pragma unroll
            for (int ks = 0; ks < 4; ks++) {
                int row = w * 16 + (lane & 15);
                int col = ks * 16 + (lane >> 4) * 8;
                ldmat4(qf[ks], sb + ATT_Q_OFF + (uint32_t)(row * ROWB + col * 2));
            }
        }

        const uint32_t kb = sb + ATT_K_OFF(s);
        const uint32_t vb = sb + ATT_V_OFF(s);

        // ---- S = Q K^T over 128 keys (log2-domain) ----
        float p[16][4];
        #pragma unroll
        for (int ni = 0; ni < 16; ni++)
            #pragma unroll
            for (int e = 0; e < 4; e++) p[ni][e] = 0.f;

        #pragma unroll
        for (int ks = 0; ks < 4; ks++) {
            #pragma unroll
            for (int np = 0; np < 8; np++) {
                uint32_t kf[4];
                int row = np * 16 + (lane & 7) + ((lane >> 4) & 1) * 8;
                int col = ks * 16 + ((lane >> 3) & 1) * 8;
                ldmat4(kf, kb + (uint32_t)(row * ROWB + col * 2));
                mma_f16(p[np*2],   qf[ks][0], qf[ks][1], qf[ks][2], qf[ks][3], kf[0], kf[1]);
                mma_f16(p[np*2+1], qf[ks][0], qf[ks][1], qf[ks][2], qf[ks][3], kf[2], kf[3]);
            }
        }

        if (kt == nk2 - 1) {
            #pragma unroll
            for (int ni = 0; ni < 16; ni++) {
                const int c = kt * 128 + ni * 8 + lc * 2;
                if (c     > row0) p[ni][0] = -1e30f;
                if (c + 1 > row0) p[ni][1] = -1e30f;
                if (c     > row1) p[ni][2] = -1e30f;
                if (c + 1 > row1) p[ni][3] = -1e30f;
            }
        }

        // ---- online softmax (base-2) ----
        float rm0 = -1e30f, rm1 = -1e30f;
        #pragma unroll
        for (int ni = 0; ni < 16; ni++) {
            rm0 = fmaxf(rm0, fmaxf(p[ni][0], p[ni][1]));
            rm1 = fmaxf(rm1, fmaxf(p[ni][2], p[ni][3]));
        }
        rm0 = fmaxf(rm0, __shfl_xor_sync(0xffffffffu, rm0, 1));
        rm0 = fmaxf(rm0, __shfl_xor_sync(0xffffffffu, rm0, 2));
        rm1 = fmaxf(rm1, __shfl_xor_sync(0xffffffffu, rm1, 1));
        rm1 = fmaxf(rm1, __shfl_xor_sync(0xffffffffu, rm1, 2));

        const float mn0 = fmaxf(m0, rm0);
        const float mn1 = fmaxf(m1, rm1);
        const float corr0 = exp2f(m0 - mn0);
        const float corr1 = exp2f(m1 - mn1);
        m0 = mn0; m1 = mn1;

        uint32_t pe0[16], pe1[16];
        float rs0 = 0.f, rs1 = 0.f;
        #pragma unroll
        for (int ni = 0; ni < 16; ni++) {
            uint32_t ea = packh2(p[ni][0] - m0, p[ni][1] - m0);
            uint32_t eb = packh2(p[ni][2] - m1, p[ni][3] - m1);
            asm("ex2.approx.f16x2 %0, %0;" : "+r"(ea));
            asm("ex2.approx.f16x2 %0, %0;" : "+r"(eb));
            pe0[ni] = ea; pe1[ni] = eb;
            float2 fa = __half22float2(*(__half2*)&ea);
            float2 fb = __half22float2(*(__half2*)&eb);
            rs0 += fa.x + fa.y;
            rs1 += fb.x + fb.y;
        }
        rs0 += __shfl_xor_sync(0xffffffffu, rs0, 1);
        rs0 += __shfl_xor_sync(0xffffffffu, rs0, 2);
        rs1 += __shfl_xor_sync(0xffffffffu, rs1, 1);
        rs1 += __shfl_xor_sync(0xffffffffu, rs1, 2);
        l0 = l0 * corr0 + rs0;
        l1 = l1 * corr1 + rs1;

        #pragma unroll
        for (int ni = 0; ni < 8; ni++) {
            o[ni][0] *= corr0; o[ni][1] *= corr0;
            o[ni][2] *= corr1; o[ni][3] *= corr1;
        }

        // ---- O += P V over k-dim 128 ----
        #pragma unroll
        for (int ks = 0; ks < 8; ks++) {
            uint32_t a0 = pe0[2*ks];
            uint32_t a1 = pe1[2*ks];
            uint32_t a2 = pe0[2*ks+1];
            uint32_t a3 = pe1[2*ks+1];
            #pragma unroll
            for (int np = 0; np < 4; np++) {
                uint32_t vf[4];
                int row = ks * 16 + (lane & 7) + ((lane >> 3) & 1) * 8;
                int col = np * 16 + ((lane >> 4) & 1) * 8;
                ldmat4t(vf, vb + (uint32_t)(row * ROWB + col * 2));
                mma_f16(o[np*2],   a0, a1, a2, a3, vf[0], vf[1]);
                mma_f16(o[np*2+1], a0, a1, a2, a3, vf[2], vf[3]);
            }
        }
    }

    const float inv0 = 1.0f / l0;
    const float inv1 = 1.0f / l1;
    const int b = bh >> 4, h = bh & 15;
    __half* y0 = g_y + ((size_t)(b * T_ + row0)) * C_ + h * D_;
    __half* y1 = g_y + ((size_t)(b * T_ + row1)) * C_ + h * D_;
    #pragma unroll
    for (int ni = 0; ni < 8; ni++) {
        const int d = ni * 8 + lc * 2;
        *(__half2*)(y0 + d) = __floats2half2_rn(o[ni][0] * inv0, o[ni][1] * inv0);
        *(__half2*)(y1 + d) = __floats2half2_rn(o[ni][2] * inv1, o[ni][3] * inv1);
    }
}

// ---------------------------------------------------------------------------
extern "C" void kernel_launch(void* const* d_in, const int* in_sizes, int n_in,
                              void* d_out, int out_size)
{
    const float* q  = (const float*)d_in[0];
    const float* k  = (const float*)d_in[1];
    const float* v  = (const float*)d_in[2];
    // d_in[3] = causal mask (unused: causality handled analytically)
    const float* Wk = (const float*)d_in[4];
    const float* bk = (const float*)d_in[5];
    const float* Wc = (const float*)d_in[6];
    const float* bc = (const float*)d_in[7];
    float* out = (float*)d_out;

    cudaFuncSetAttribute(proj_h_kernel,
                         cudaFuncAttributeMaxDynamicSharedMemorySize, SMEM_PROJ_BYTES);
    cudaFuncSetAttribute(outproj_h_kernel,
                         cudaFuncAttributeMaxDynamicSharedMemorySize, SMEM_OUT_BYTES);
    cudaFuncSetAttribute(attn_h_kernel,
                         cudaFuncAttributeMaxDynamicSharedMemorySize, ATT_SMEM_BYTES);

    // 0) fp32 -> fp16 conversion of all GEMM operands
    cvt_kernel<<<dim3((M_*C_)/(256*4), 5), 256>>>(q, k, v, Wk, Wc);

    // 1) fused Q/K/V projection (128x128 tiles, 64x64 warp tiles)
    proj_h_kernel<<<dim3(C_/128, M_/128, 3), 128, SMEM_PROJ_BYTES>>>(bk);

    // 2) fp16 tensor-core causal flash attention (KN=128) -> g_y fp16
    attn_h_kernel<<<dim3(16, 32), 128, ATT_SMEM_BYTES>>>();

    // 3) output projection (128x64 tiles) -> fp32 d_out
    outproj_h_kernel<<<dim3(C_/64, M_/128, 1), 128, SMEM_OUT_BYTES>>>(bc, out);
}